// round 3
// baseline (speedup 1.0000x reference)
#include <cuda_runtime.h>
#include <cuda_fp16.h>
#include <cstdint>

#define BATCHN 8192
#define OUTF   512
#define KSEG   768
#define NROWS  2048
#define NCHUNK 36

#define BM 128
#define BN 256
#define BK 64
#define STAGES 3
#define STAGE_BYTES 49152          // A 16KB + B 32KB
#define A_BYTES 16384
#define SMEM_TOTAL (STAGES * STAGE_BYTES)   // 147456; epilogue D (135168) reuses it
#define DPITCH 264                 // padded f32 row stride for epilogue

// ---------------- static device scratch (allocation-rule-safe) -------------
__device__ __align__(128) __half g_Uh[BATCHN * KSEG];
__device__ __align__(128) __half g_Ul[BATCHN * KSEG];
__device__ __align__(128) __half g_Wh[NROWS * KSEG];
__device__ __align__(128) __half g_Wl[NROWS * KSEG];

// ---------------- PTX helpers ----------------------------------------------
__device__ __forceinline__ uint32_t smem_u32(const void* p) {
    uint32_t a;
    asm("{ .reg .u64 t; cvta.to.shared.u64 t, %1; cvt.u32.u64 %0, t; }"
        : "=r"(a) : "l"(p));
    return a;
}
__device__ __forceinline__ void cpa16(uint32_t dst, const void* src) {
    asm volatile("cp.async.cg.shared.global [%0], [%1], 16;" :: "r"(dst), "l"(src));
}
#define CP_COMMIT() asm volatile("cp.async.commit_group;" ::: "memory")
#define CP_WAIT(n)  asm volatile("cp.async.wait_group %0;" :: "n"(n) : "memory")

#define LDSM4(r, a)                                                             \
    asm volatile("ldmatrix.sync.aligned.m8n8.x4.shared.b16 {%0,%1,%2,%3}, [%4];"\
                 : "=r"((r)[0]), "=r"((r)[1]), "=r"((r)[2]), "=r"((r)[3])       \
                 : "r"(a))

#define MMA16816(c, a, b0, b1)                                                  \
    asm volatile("mma.sync.aligned.m16n8k16.row.col.f32.f16.f16.f32 "           \
                 "{%0,%1,%2,%3}, {%4,%5,%6,%7}, {%8,%9}, {%0,%1,%2,%3};"        \
                 : "+f"((c)[0]), "+f"((c)[1]), "+f"((c)[2]), "+f"((c)[3])       \
                 : "r"((a)[0]), "r"((a)[1]), "r"((a)[2]), "r"((a)[3]),          \
                   "r"(b0), "r"(b1))

__device__ __forceinline__ float sigf(float z) { return 1.f / (1.f + __expf(-z)); }
__device__ __forceinline__ float tanhf_fast(float z) {
    return 1.f - 2.f / (__expf(2.f * z) + 1.f);
}

// ---------------- prep kernels ---------------------------------------------
// W'[row = 4*o + g][k] : k<512 -> W_h[g][o][k] ; k>=512 -> W_x[g][o][k-512]
__global__ void prep_w_kernel(
    const float* __restrict__ w0h, const float* __restrict__ w0x,
    const float* __restrict__ w1h, const float* __restrict__ w1x,
    const float* __restrict__ w2h, const float* __restrict__ w2x,
    const float* __restrict__ w3h, const float* __restrict__ w3x)
{
    int idx = blockIdx.x * 256 + threadIdx.x;
    if (idx >= NROWS * KSEG) return;
    int rw = idx / KSEG;
    int k  = idx - rw * KSEG;
    int o  = rw >> 2, g = rw & 3;
    const float* ph; const float* px;
    switch (g) {
        case 0:  ph = w0h; px = w0x; break;
        case 1:  ph = w1h; px = w1x; break;
        case 2:  ph = w2h; px = w2x; break;
        default: ph = w3h; px = w3x; break;
    }
    float v = (k < 512) ? ph[o * 512 + k] : px[o * 256 + (k - 512)];
    __half hi = __float2half(v);
    g_Wh[idx] = hi;
    g_Wl[idx] = __float2half(v - __half2float(hi));
}

// U[b][k] : k<512 -> H[b][k] ; k>=512 -> x[b][n][k-512]
__global__ void prep_u_kernel(const float* __restrict__ x,
                              const float* __restrict__ H,
                              const int* __restrict__ np)
{
    int i = blockIdx.x * 256 + threadIdx.x;
    if (i >= BATCHN * (KSEG / 4)) return;
    int b  = i / (KSEG / 4);
    int k4 = (i - b * (KSEG / 4)) * 4;
    float4 v;
    if (k4 < 512) {
        v = *(const float4*)(H + (size_t)b * 512 + k4);
    } else {
        int n = *np;
        v = *(const float4*)(x + (size_t)b * 4096 + n * 256 + (k4 - 512));
    }
    float vv[4] = {v.x, v.y, v.z, v.w};
    union { __half h[4]; uint2 u; } phh, pll;
#pragma unroll
    for (int j = 0; j < 4; ++j) {
        phh.h[j] = __float2half(vv[j]);
        pll.h[j] = __float2half(vv[j] - __half2float(phh.h[j]));
    }
    size_t p = (size_t)b * KSEG + k4;
    *(uint2*)(g_Uh + p) = phh.u;
    *(uint2*)(g_Ul + p) = pll.u;
}

// ---------------- GEMM + fused LSTM epilogue -------------------------------
// chunk c: seg = c/12 (0: Uh*Wh, 1: Ul*Wh, 2: Uh*Wl), kk = (c%12)*64
__device__ __forceinline__ void load_chunk(uint32_t sb, int stg, int c,
                                           int bx, int by, int tid) {
    int seg = c / 12;
    int kk  = (c - seg * 12) * BK;
    const __half* As = (seg == 1) ? g_Ul : g_Uh;
    const __half* Bs = (seg == 2) ? g_Wl : g_Wh;
    uint32_t aA = sb + stg * STAGE_BYTES;
    uint32_t aB = aA + A_BYTES;
#pragma unroll
    for (int it = 0; it < 12; ++it) {
        int u = it * 256 + tid;
        if (u < 1024) {                       // A: 128 rows x 8 x 16B
            int r = u >> 3, i = u & 7;
            uint32_t off = (uint32_t)(r * 128 + i * 16);
            uint32_t sw  = off ^ (((uint32_t)(r & 7)) << 4);
            cpa16(aA + sw, (const char*)(As + (size_t)(bx * BM + r) * KSEG + kk) + i * 16);
        } else {                              // B: 256 rows x 8 x 16B
            int v = u - 1024;
            int r = v >> 3, i = v & 7;
            uint32_t off = (uint32_t)(r * 128 + i * 16);
            uint32_t sw  = off ^ (((uint32_t)(r & 7)) << 4);
            cpa16(aB + sw, (const char*)(Bs + (size_t)(by * BN + r) * KSEG + kk) + i * 16);
        }
    }
    CP_COMMIT();
}

__global__ void __launch_bounds__(256, 1)
lstm_gemm(const float* __restrict__ C,
          const float* __restrict__ fg_w_c, const float* __restrict__ fg_b,
          const float* __restrict__ ig_w_c, const float* __restrict__ ig_b,
          const float* __restrict__ in_b,
          const float* __restrict__ og_w_cn, const float* __restrict__ og_b,
          float* __restrict__ out)
{
    extern __shared__ __align__(1024) char smem[];
    uint32_t sb = smem_u32(smem);
    const int tid = threadIdx.x;
    const int l   = tid & 31;
    const int w   = tid >> 5;
    const int bx  = blockIdx.x;   // 0..63 batch tile
    const int by  = blockIdx.y;   // 0..7  N tile

    const int wm0 = (w >> 2) * 64;   // warp M origin
    const int wn0 = (w & 3) * 64;    // warp N origin

    // ldmatrix per-lane bases
    const int arow  = wm0 + (l & 7) + ((l >> 3) & 1) * 8;
    const int akoff = (l >> 4) * 16;
    const int brow  = wn0 + (l & 7) + ((l >> 4) & 1) * 8;
    const int bkoff = ((l >> 3) & 1) * 16;
    const uint32_t swz = (uint32_t)((l & 7) << 4);

    float acc[4][8][4];
#pragma unroll
    for (int a = 0; a < 4; ++a)
#pragma unroll
        for (int b = 0; b < 8; ++b)
#pragma unroll
            for (int d = 0; d < 4; ++d) acc[a][b][d] = 0.f;

    // prologue: chunks 0,1
    load_chunk(sb, 0, 0, bx, by, tid);
    load_chunk(sb, 1, 1, bx, by, tid);

    for (int c = 0; c < NCHUNK; ++c) {
        CP_WAIT(1);
        __syncthreads();
        if (c + 2 < NCHUNK) load_chunk(sb, (c + 2) % STAGES, c + 2, bx, by, tid);

        uint32_t sA = sb + (c % STAGES) * STAGE_BYTES;
        uint32_t sB = sA + A_BYTES;
#pragma unroll
        for (int ks = 0; ks < 4; ++ks) {
            uint32_t af[4][4], bf[4][4];
#pragma unroll
            for (int mi = 0; mi < 4; ++mi) {
                uint32_t kb = (uint32_t)(ks * 32 + akoff) ^ swz;
                LDSM4(af[mi], sA + (uint32_t)((arow + mi * 16) * 128) + kb);
            }
#pragma unroll
            for (int nj = 0; nj < 4; ++nj) {
                uint32_t kb = (uint32_t)(ks * 32 + bkoff) ^ swz;
                LDSM4(bf[nj], sB + (uint32_t)((brow + nj * 16) * 128) + kb);
            }
#pragma unroll
            for (int mi = 0; mi < 4; ++mi) {
#pragma unroll
                for (int nj = 0; nj < 4; ++nj) {
                    MMA16816(acc[mi][nj * 2 + 0], af[mi], bf[nj][0], bf[nj][1]);
                    MMA16816(acc[mi][nj * 2 + 1], af[mi], bf[nj][2], bf[nj][3]);
                }
            }
        }
    }

    // ---------------- epilogue ---------------------------------------------
    __syncthreads();   // all compute done; reuse smem for D tile
    float* Ds = (float*)smem;
#pragma unroll
    for (int mi = 0; mi < 4; ++mi) {
#pragma unroll
        for (int cj = 0; cj < 8; ++cj) {
            int r0 = wm0 + mi * 16 + (l >> 2);
            int cb = wn0 + cj * 8 + (l & 3) * 2;
            Ds[r0 * DPITCH + cb]       = acc[mi][cj][0];
            Ds[r0 * DPITCH + cb + 1]   = acc[mi][cj][1];
            Ds[(r0 + 8) * DPITCH + cb]     = acc[mi][cj][2];
            Ds[(r0 + 8) * DPITCH + cb + 1] = acc[mi][cj][3];
        }
    }
    __syncthreads();

    const int ol = tid & 63;          // local output feature 0..63
    const int m0 = tid >> 6;          // 0..3
    const int og = by * 64 + ol;      // global output feature
    const float wcf = fg_w_c[og], wci = ig_w_c[og], wco = og_w_cn[og];
    const float bff = fg_b[og], bii = ig_b[og], bnn = in_b[og], boo = og_b[og];

#pragma unroll 4
    for (int r = 0; r < 32; ++r) {
        int m = m0 * 32 + r;
        int b = bx * BM + m;
        float4 z = *(const float4*)&Ds[m * DPITCH + ol * 4];
        float Cv = C[(size_t)b * OUTF + og];
        float zf = z.x + wcf * Cv + bff;
        float zi = z.y + wci * Cv + bii;
        float zn = z.z + bnn;
        float cm = sigf(zf) * Cv + sigf(zi) * tanhf_fast(zn);
        float zo = z.w + wco * cm + boo;
        float h  = sigf(zo) * tanhf_fast(cm);
        out[(size_t)b * OUTF + og] = cm;
        out[(size_t)BATCHN * OUTF + (size_t)b * OUTF + og] = h;
    }
}

// ---------------- launch ----------------------------------------------------
extern "C" void kernel_launch(void* const* d_in, const int* in_sizes, int n_in,
                              void* d_out, int out_size) {
    const float* x      = (const float*)d_in[0];
    const float* C      = (const float*)d_in[1];
    const float* H      = (const float*)d_in[2];
    const float* fg_w_c = (const float*)d_in[3];
    const float* fg_w_h = (const float*)d_in[4];
    const float* fg_w_x = (const float*)d_in[5];
    const float* fg_b   = (const float*)d_in[6];
    const float* ig_w_c = (const float*)d_in[7];
    const float* ig_w_h = (const float*)d_in[8];
    const float* ig_w_x = (const float*)d_in[9];
    const float* ig_b   = (const float*)d_in[10];
    const float* in_w_h = (const float*)d_in[11];
    const float* in_w_x = (const float*)d_in[12];
    const float* in_b   = (const float*)d_in[13];
    const float* og_w_cn= (const float*)d_in[14];
    const float* og_w_h = (const float*)d_in[15];
    const float* og_w_x = (const float*)d_in[16];
    const float* og_b   = (const float*)d_in[17];
    const int*   n      = (const int*)d_in[18];
    float* out = (float*)d_out;

    prep_w_kernel<<<(NROWS * KSEG + 255) / 256, 256>>>(
        fg_w_h, fg_w_x, ig_w_h, ig_w_x, in_w_h, in_w_x, og_w_h, og_w_x);
    prep_u_kernel<<<(BATCHN * (KSEG / 4) + 255) / 256, 256>>>(x, H, n);

    static bool attr_done = false;
    if (!attr_done) {
        cudaFuncSetAttribute(lstm_gemm,
                             cudaFuncAttributeMaxDynamicSharedMemorySize, SMEM_TOTAL);
        attr_done = true;
    }
    dim3 grid(BATCHN / BM, NROWS / BN);
    lstm_gemm<<<grid, 256, SMEM_TOTAL>>>(
        C, fg_w_c, fg_b, ig_w_c, ig_b, in_b, og_w_cn, og_b, out);
}

// round 4
// speedup vs baseline: 1.2772x; 1.2772x over previous
#include <cuda_runtime.h>
#include <cuda_fp16.h>
#include <cstdint>

#define BATCHN 8192
#define OUTF   512
#define KSEG   768
#define NROWS  2048
#define NCHUNK 24            // 2 segments x 12 chunks of K=64

#define BM 128
#define BN 256
#define BK 64
#define STAGES 4
#define STAGE_BYTES 49152    // A 16KB + B 32KB
#define A_BYTES 16384
#define SMEM_TOTAL (STAGES * STAGE_BYTES)   // 196608; epilogue D (135KB) reuses it
#define DPITCH 264           // padded f32 row stride for epilogue

// ---------------- static device scratch (allocation-rule-safe) -------------
__device__ __align__(128) __half g_Uh[BATCHN * KSEG];
__device__ __align__(128) __half g_Ul[BATCHN * KSEG];
__device__ __align__(128) __half g_Wh[NROWS * KSEG];

// ---------------- PTX helpers ----------------------------------------------
__device__ __forceinline__ uint32_t smem_u32(const void* p) {
    uint32_t a;
    asm("{ .reg .u64 t; cvta.to.shared.u64 t, %1; cvt.u32.u64 %0, t; }"
        : "=r"(a) : "l"(p));
    return a;
}
__device__ __forceinline__ void cpa16(uint32_t dst, const void* src) {
    asm volatile("cp.async.cg.shared.global [%0], [%1], 16;" :: "r"(dst), "l"(src));
}
#define CP_COMMIT() asm volatile("cp.async.commit_group;" ::: "memory")
#define CP_WAIT(n)  asm volatile("cp.async.wait_group %0;" :: "n"(n) : "memory")

#define LDSM4(r, a)                                                             \
    asm volatile("ldmatrix.sync.aligned.m8n8.x4.shared.b16 {%0,%1,%2,%3}, [%4];"\
                 : "=r"((r)[0]), "=r"((r)[1]), "=r"((r)[2]), "=r"((r)[3])       \
                 : "r"(a))

#define MMA16816(c, a, b0, b1)                                                  \
    asm volatile("mma.sync.aligned.m16n8k16.row.col.f32.f16.f16.f32 "           \
                 "{%0,%1,%2,%3}, {%4,%5,%6,%7}, {%8,%9}, {%0,%1,%2,%3};"        \
                 : "+f"((c)[0]), "+f"((c)[1]), "+f"((c)[2]), "+f"((c)[3])       \
                 : "r"((a)[0]), "r"((a)[1]), "r"((a)[2]), "r"((a)[3]),          \
                   "r"(b0), "r"(b1))

__device__ __forceinline__ float sigf(float z) { return 1.f / (1.f + __expf(-z)); }
__device__ __forceinline__ float tanhf_fast(float z) {
    return 1.f - 2.f / (__expf(2.f * z) + 1.f);
}

// ---------------- prep kernels ---------------------------------------------
// W'[row = 4*o + g][k] : k<512 -> W_h[g][o][k] ; k>=512 -> W_x[g][o][k-512]
__global__ void prep_w_kernel(
    const float* __restrict__ w0h, const float* __restrict__ w0x,
    const float* __restrict__ w1h, const float* __restrict__ w1x,
    const float* __restrict__ w2h, const float* __restrict__ w2x,
    const float* __restrict__ w3h, const float* __restrict__ w3x)
{
    int i = blockIdx.x * 256 + threadIdx.x;
    if (i >= NROWS * (KSEG / 4)) return;
    int rw = i / (KSEG / 4);
    int k4 = (i - rw * (KSEG / 4)) * 4;
    int o  = rw >> 2, g = rw & 3;
    const float* ph; const float* px;
    switch (g) {
        case 0:  ph = w0h; px = w0x; break;
        case 1:  ph = w1h; px = w1x; break;
        case 2:  ph = w2h; px = w2x; break;
        default: ph = w3h; px = w3x; break;
    }
    float4 v = (k4 < 512) ? *(const float4*)(ph + o * 512 + k4)
                          : *(const float4*)(px + o * 256 + (k4 - 512));
    float vv[4] = {v.x, v.y, v.z, v.w};
    union { __half h[4]; uint2 u; } p;
#pragma unroll
    for (int j = 0; j < 4; ++j) p.h[j] = __float2half(vv[j]);
    *(uint2*)(g_Wh + (size_t)rw * KSEG + k4) = p.u;
}

// U[b][k] : k<512 -> H[b][k] ; k>=512 -> x[b][n][k-512]; fp16 hi/lo split
__global__ void prep_u_kernel(const float* __restrict__ x,
                              const float* __restrict__ H,
                              const int* __restrict__ np)
{
    int i = blockIdx.x * 256 + threadIdx.x;
    if (i >= BATCHN * (KSEG / 4)) return;
    int b  = i / (KSEG / 4);
    int k4 = (i - b * (KSEG / 4)) * 4;
    float4 v;
    if (k4 < 512) {
        v = *(const float4*)(H + (size_t)b * 512 + k4);
    } else {
        int n = *np;
        v = *(const float4*)(x + (size_t)b * 4096 + n * 256 + (k4 - 512));
    }
    float vv[4] = {v.x, v.y, v.z, v.w};
    union { __half h[4]; uint2 u; } phh, pll;
#pragma unroll
    for (int j = 0; j < 4; ++j) {
        phh.h[j] = __float2half(vv[j]);
        pll.h[j] = __float2half(vv[j] - __half2float(phh.h[j]));
    }
    size_t p = (size_t)b * KSEG + k4;
    *(uint2*)(g_Uh + p) = phh.u;
    *(uint2*)(g_Ul + p) = pll.u;
}

// ---------------- GEMM + fused LSTM epilogue -------------------------------
// chunk c: seg = c/12 (0: Uh*Wh, 1: Ul*Wh), kk = (c%12)*64
__device__ __forceinline__ void load_chunk(uint32_t sb, int stg, int c,
                                           int bx, int by, int tid) {
    int seg = c / 12;
    int kk  = (c - seg * 12) * BK;
    const __half* As = (seg == 1) ? g_Ul : g_Uh;
    const __half* Bs = g_Wh;
    uint32_t aA = sb + stg * STAGE_BYTES;
    uint32_t aB = aA + A_BYTES;
#pragma unroll
    for (int it = 0; it < 12; ++it) {
        int u = it * 256 + tid;
        if (u < 1024) {                       // A: 128 rows x 8 x 16B
            int r = u >> 3, i = u & 7;
            uint32_t off = (uint32_t)(r * 128 + i * 16);
            uint32_t sw  = off ^ (((uint32_t)(r & 7)) << 4);
            cpa16(aA + sw, (const char*)(As + (size_t)(bx * BM + r) * KSEG + kk) + i * 16);
        } else {                              // B: 256 rows x 8 x 16B
            int v = u - 1024;
            int r = v >> 3, i = v & 7;
            uint32_t off = (uint32_t)(r * 128 + i * 16);
            uint32_t sw  = off ^ (((uint32_t)(r & 7)) << 4);
            cpa16(aB + sw, (const char*)(Bs + (size_t)(by * BN + r) * KSEG + kk) + i * 16);
        }
    }
    CP_COMMIT();
}

__global__ void __launch_bounds__(256, 1)
lstm_gemm(const float* __restrict__ C,
          const float* __restrict__ fg_w_c, const float* __restrict__ fg_b,
          const float* __restrict__ ig_w_c, const float* __restrict__ ig_b,
          const float* __restrict__ in_b,
          const float* __restrict__ og_w_cn, const float* __restrict__ og_b,
          float* __restrict__ out)
{
    extern __shared__ __align__(1024) char smem[];
    uint32_t sb = smem_u32(smem);
    const int tid = threadIdx.x;
    const int l   = tid & 31;
    const int w   = tid >> 5;
    const int bx  = blockIdx.x;   // 0..63 batch tile
    const int by  = blockIdx.y;   // 0..7  N tile

    const int wm0 = (w >> 2) * 64;   // warp M origin
    const int wn0 = (w & 3) * 64;    // warp N origin

    // ldmatrix per-lane bases
    const int arow  = wm0 + (l & 7) + ((l >> 3) & 1) * 8;
    const int akoff = (l >> 4) * 16;
    const int brow  = wn0 + (l & 7) + ((l >> 4) & 1) * 8;
    const int bkoff = ((l >> 3) & 1) * 16;
    const uint32_t swz = (uint32_t)((l & 7) << 4);

    float acc[4][8][4];
#pragma unroll
    for (int a = 0; a < 4; ++a)
#pragma unroll
        for (int b = 0; b < 8; ++b)
#pragma unroll
            for (int d = 0; d < 4; ++d) acc[a][b][d] = 0.f;

    // prologue: stage chunks 0,1,2
    load_chunk(sb, 0, 0, bx, by, tid);
    load_chunk(sb, 1, 1, bx, by, tid);
    load_chunk(sb, 2, 2, bx, by, tid);

    uint32_t af[2][4][4], bf[2][4][4];

    for (int c = 0; c < NCHUNK; ++c) {
        CP_WAIT(2);                 // chunk c resident (one commit per iter below)
        __syncthreads();
        if (c + 3 < NCHUNK) load_chunk(sb, (c + 3) % STAGES, c + 3, bx, by, tid);
        else                CP_COMMIT();   // empty group keeps wait accounting exact

        uint32_t sA = sb + (c % STAGES) * STAGE_BYTES;
        uint32_t sB = sA + A_BYTES;

        // prefetch fragments for ks=0
#pragma unroll
        for (int mi = 0; mi < 4; ++mi)
            LDSM4(af[0][mi], sA + (uint32_t)((arow + mi * 16) * 128)
                               + ((uint32_t)akoff ^ swz));
#pragma unroll
        for (int nj = 0; nj < 4; ++nj)
            LDSM4(bf[0][nj], sB + (uint32_t)((brow + nj * 16) * 128)
                               + ((uint32_t)bkoff ^ swz));

#pragma unroll
        for (int ks = 0; ks < 4; ++ks) {
            int cur = ks & 1, nxt = cur ^ 1;
            if (ks < 3) {           // prefetch ks+1 while MMAs of ks run
                uint32_t ka = (uint32_t)((ks + 1) * 32 + akoff) ^ swz;
                uint32_t kb = (uint32_t)((ks + 1) * 32 + bkoff) ^ swz;
#pragma unroll
                for (int mi = 0; mi < 4; ++mi)
                    LDSM4(af[nxt][mi], sA + (uint32_t)((arow + mi * 16) * 128) + ka);
#pragma unroll
                for (int nj = 0; nj < 4; ++nj)
                    LDSM4(bf[nxt][nj], sB + (uint32_t)((brow + nj * 16) * 128) + kb);
            }
#pragma unroll
            for (int mi = 0; mi < 4; ++mi) {
#pragma unroll
                for (int nj = 0; nj < 4; ++nj) {
                    MMA16816(acc[mi][nj * 2 + 0], af[cur][mi], bf[cur][nj][0], bf[cur][nj][1]);
                    MMA16816(acc[mi][nj * 2 + 1], af[cur][mi], bf[cur][nj][2], bf[cur][nj][3]);
                }
            }
        }
    }

    // ---------------- epilogue ---------------------------------------------
    __syncthreads();   // all compute done; reuse smem for D tile
    float* Ds = (float*)smem;
#pragma unroll
    for (int mi = 0; mi < 4; ++mi) {
#pragma unroll
        for (int cj = 0; cj < 8; ++cj) {
            int r0 = wm0 + mi * 16 + (l >> 2);
            int cb = wn0 + cj * 8 + (l & 3) * 2;
            Ds[r0 * DPITCH + cb]           = acc[mi][cj][0];
            Ds[r0 * DPITCH + cb + 1]       = acc[mi][cj][1];
            Ds[(r0 + 8) * DPITCH + cb]     = acc[mi][cj][2];
            Ds[(r0 + 8) * DPITCH + cb + 1] = acc[mi][cj][3];
        }
    }
    __syncthreads();

    const int ol = tid & 63;          // local output feature 0..63
    const int m0 = tid >> 6;          // 0..3
    const int og = by * 64 + ol;      // global output feature
    const float wcf = fg_w_c[og], wci = ig_w_c[og], wco = og_w_cn[og];
    const float bff = fg_b[og], bii = ig_b[og], bnn = in_b[og], boo = og_b[og];

#pragma unroll 4
    for (int r = 0; r < 32; ++r) {
        int m = m0 * 32 + r;
        int b = bx * BM + m;
        float4 z = *(const float4*)&Ds[m * DPITCH + ol * 4];
        float Cv = C[(size_t)b * OUTF + og];
        float zf = z.x + wcf * Cv + bff;
        float zi = z.y + wci * Cv + bii;
        float zn = z.z + bnn;
        float cm = sigf(zf) * Cv + sigf(zi) * tanhf_fast(zn);
        float zo = z.w + wco * cm + boo;
        float h  = sigf(zo) * tanhf_fast(cm);
        out[(size_t)b * OUTF + og] = cm;
        out[(size_t)BATCHN * OUTF + (size_t)b * OUTF + og] = h;
    }
}

// ---------------- launch ----------------------------------------------------
extern "C" void kernel_launch(void* const* d_in, const int* in_sizes, int n_in,
                              void* d_out, int out_size) {
    const float* x      = (const float*)d_in[0];
    const float* C      = (const float*)d_in[1];
    const float* H      = (const float*)d_in[2];
    const float* fg_w_c = (const float*)d_in[3];
    const float* fg_w_h = (const float*)d_in[4];
    const float* fg_w_x = (const float*)d_in[5];
    const float* fg_b   = (const float*)d_in[6];
    const float* ig_w_c = (const float*)d_in[7];
    const float* ig_w_h = (const float*)d_in[8];
    const float* ig_w_x = (const float*)d_in[9];
    const float* ig_b   = (const float*)d_in[10];
    const float* in_w_h = (const float*)d_in[11];
    const float* in_w_x = (const float*)d_in[12];
    const float* in_b   = (const float*)d_in[13];
    const float* og_w_cn= (const float*)d_in[14];
    const float* og_w_h = (const float*)d_in[15];
    const float* og_w_x = (const float*)d_in[16];
    const float* og_b   = (const float*)d_in[17];
    const int*   n      = (const int*)d_in[18];
    float* out = (float*)d_out;

    prep_w_kernel<<<(NROWS * (KSEG / 4) + 255) / 256, 256>>>(
        fg_w_h, fg_w_x, ig_w_h, ig_w_x, in_w_h, in_w_x, og_w_h, og_w_x);
    prep_u_kernel<<<(BATCHN * (KSEG / 4) + 255) / 256, 256>>>(x, H, n);

    static bool attr_done = false;
    if (!attr_done) {
        cudaFuncSetAttribute(lstm_gemm,
                             cudaFuncAttributeMaxDynamicSharedMemorySize, SMEM_TOTAL);
        attr_done = true;
    }
    dim3 grid(BATCHN / BM, NROWS / BN);
    lstm_gemm<<<grid, 256, SMEM_TOTAL>>>(
        C, fg_w_c, fg_b, ig_w_c, ig_b, in_b, og_w_cn, og_b, out);
}